// round 1
// baseline (speedup 1.0000x reference)
#include <cuda_runtime.h>
#include <cstdint>

// out[b,o] = sum_i x[b,i] * (sum_p coef[o,i,p]) * weights[o,i]
//  Phase 1: w_eff^T[i][o] = (sum_p coef[o,i,p]) * weights[o,i]   (scratch, 4MB)
//  Phase 2: out[8192,1024] = x[8192,1024] @ w_eff^T[1024,1024]   (fp32 GEMM)

#define BATCH 8192
#define IN    1024
#define OUT   1024
#define PDIM  8

// scratch for B = w_eff^T  (K=IN rows, N=OUT cols), static device alloc (allowed)
__device__ float g_wt[IN * OUT];

// ---------------------------------------------------------------------------
// f32x2 packed helpers (Blackwell-only; ptxas never emits FFMA2 from C++)
// ---------------------------------------------------------------------------
typedef unsigned long long u64;

__device__ __forceinline__ u64 pack2(float x, float y) {
    u64 r;
    asm("mov.b64 %0, {%1, %2};" : "=l"(r) : "f"(x), "f"(y));
    return r;
}

__device__ __forceinline__ u64 ffma2(u64 a, u64 b, u64 c) {
    u64 d;
    asm("fma.rn.f32x2 %0, %1, %2, %3;" : "=l"(d) : "l"(a), "l"(b), "l"(c));
    return d;
}

// ---------------------------------------------------------------------------
// Phase 1: w_eff^T
// thread idx -> (o, i); coef read: 32B contiguous per thread, consecutive
// threads contiguous (perfectly coalesced). weights coalesced. wt write is
// strided (transpose) -> ~128MB effective traffic, ~16us. Acceptable.
// ---------------------------------------------------------------------------
__global__ __launch_bounds__(256) void weff_kernel(
    const float* __restrict__ coef,
    const float* __restrict__ w)
{
    int idx = blockIdx.x * 256 + threadIdx.x;       // over O*I
    int o = idx >> 10;          // / IN
    int i = idx & 1023;         // % IN
    const float4* c4 = reinterpret_cast<const float4*>(coef + (size_t)idx * PDIM);
    float4 a = c4[0];
    float4 b = c4[1];
    float s = ((a.x + a.y) + (a.z + a.w)) + ((b.x + b.y) + (b.z + b.w));
    g_wt[i * OUT + o] = s * w[idx];
}

// ---------------------------------------------------------------------------
// Phase 2: SGEMM  C[M,N] = A[M,K] * B[K,N]
// M=8192, N=1024, K=1024. Block tile 128x128x16, 256 threads, 8x8 per thread,
// accumulators packed along N as f32x2 (32 FFMA2 per k-step per thread).
// ---------------------------------------------------------------------------
#define BM 128
#define BN 128
#define BK 16
#define TM 8
#define TN 8

__global__ __launch_bounds__(256) void sgemm_f32x2(
    const float* __restrict__ A,
    float* __restrict__ C)
{
    __shared__ float As[BK][BM];      // transposed A tile: As[k][m]
    __shared__ float Bs[BK][BN];      // Bs[k][n]

    const int tid = threadIdx.x;
    const int bm  = blockIdx.y * BM;
    const int bn  = blockIdx.x * BN;
    const int tx  = tid & 15;         // N direction (16)
    const int ty  = tid >> 4;         // M direction (16)

    // A-tile load mapping: 128 rows x 4 float4-cols = 512 float4s, 2 per thread
    const int a_row = tid >> 1;            // 0..127
    const int a_c4b = (tid & 1) * 2;       // float4 col base: 0 or 2

    // B-tile load mapping: 16 rows x 32 float4-cols = 512 float4s, 2 per thread
    const int b_f0 = tid * 2;

    u64 acc[TM][TN / 2];
    #pragma unroll
    for (int i = 0; i < TM; i++)
        #pragma unroll
        for (int j = 0; j < TN / 2; j++)
            acc[i][j] = 0ULL;

    const float* Bsrc = g_wt;

    for (int k0 = 0; k0 < IN; k0 += BK) {
        // --- load A tile (transpose into As[k][m]) ---
        #pragma unroll
        for (int q = 0; q < 2; q++) {
            int c4 = a_c4b + q;
            float4 v = *reinterpret_cast<const float4*>(
                &A[(size_t)(bm + a_row) * IN + k0 + c4 * 4]);
            As[c4 * 4 + 0][a_row] = v.x;
            As[c4 * 4 + 1][a_row] = v.y;
            As[c4 * 4 + 2][a_row] = v.z;
            As[c4 * 4 + 3][a_row] = v.w;
        }
        // --- load B tile ---
        #pragma unroll
        for (int q = 0; q < 2; q++) {
            int f  = b_f0 + q;
            int r  = f >> 5;          // /32
            int c4 = f & 31;
            *reinterpret_cast<float4*>(&Bs[r][c4 * 4]) =
                *reinterpret_cast<const float4*>(
                    &Bsrc[(size_t)(k0 + r) * OUT + bn + c4 * 4]);
        }
        __syncthreads();

        #pragma unroll
        for (int kk = 0; kk < BK; kk++) {
            // b fragment: 4 packed f32x2 (8-byte-aligned LDS.64)
            u64 b2[4];
            #pragma unroll
            for (int j = 0; j < 4; j++)
                b2[j] = *reinterpret_cast<const u64*>(&Bs[kk][tx * 8 + j * 2]);

            // a fragment: 8 floats via two LDS.128
            float4 av0 = *reinterpret_cast<const float4*>(&As[kk][ty * 8]);
            float4 av1 = *reinterpret_cast<const float4*>(&As[kk][ty * 8 + 4]);
            float a[TM] = {av0.x, av0.y, av0.z, av0.w, av1.x, av1.y, av1.z, av1.w};

            #pragma unroll
            for (int i = 0; i < TM; i++) {
                u64 a2 = pack2(a[i], a[i]);
                #pragma unroll
                for (int j = 0; j < 4; j++)
                    acc[i][j] = ffma2(a2, b2[j], acc[i][j]);
            }
        }
        __syncthreads();
    }

    // --- epilogue: packed pairs are exactly adjacent C columns ---
    #pragma unroll
    for (int i = 0; i < TM; i++) {
        float* crow = &C[(size_t)(bm + ty * 8 + i) * OUT + bn + tx * 8];
        #pragma unroll
        for (int j = 0; j < 4; j++)
            *reinterpret_cast<u64*>(crow + j * 2) = acc[i][j];
    }
}

// ---------------------------------------------------------------------------
extern "C" void kernel_launch(void* const* d_in, const int* in_sizes, int n_in,
                              void* d_out, int out_size)
{
    const float* x    = (const float*)d_in[0];   // [8192,1024]
    const float* coef = (const float*)d_in[1];   // [1024,1024,8]
    const float* w    = (const float*)d_in[2];   // [1024,1024]
    float* out        = (float*)d_out;           // [8192,1024]

    (void)in_sizes; (void)n_in; (void)out_size;

    weff_kernel<<<(OUT * IN) / 256, 256>>>(coef, w);

    dim3 grid(OUT / BN, BATCH / BM);   // (8, 64)
    sgemm_f32x2<<<grid, 256>>>(x, out);
}

// round 4
// speedup vs baseline: 1.4896x; 1.4896x over previous
#include <cuda_runtime.h>
#include <cuda_bf16.h>
#include <cstdint>

// out[b,o] = x @ w_eff^T,  w_eff[o,i] = (sum_p coef[o,i,p]) * weights[o,i]
// bf16 hi/lo 3-GEMM split on HMMA (mma.sync m16n8k16), folded into one K=3072 loop:
//   k in [0,1024):    A_hi * B_hi
//   k in [1024,2048): A_lo * B_hi
//   k in [2048,3072): A_hi * B_lo

#define BATCH 8192
#define IN    1024
#define OUT   1024
#define PDIM  8

// ---- static scratch (allowed) ----
__device__ __nv_bfloat16 g_ahi[BATCH * IN];
__device__ __nv_bfloat16 g_alo[BATCH * IN];
__device__ __nv_bfloat16 g_bhi[OUT * IN];   // [O,I] row-major == B^T [N,K]
__device__ __nv_bfloat16 g_blo[OUT * IN];

// ============================ prep kernels ============================
__global__ __launch_bounds__(256) void xsplit_kernel(const float* __restrict__ x) {
    int idx = blockIdx.x * 256 + threadIdx.x;          // over BATCH*IN/4
    float4 v = reinterpret_cast<const float4*>(x)[idx];
    union { __nv_bfloat16 h[4]; uint2 u; } hi, lo;
    float f[4] = {v.x, v.y, v.z, v.w};
#pragma unroll
    for (int j = 0; j < 4; j++) {
        __nv_bfloat16 h = __float2bfloat16(f[j]);
        hi.h[j] = h;
        lo.h[j] = __float2bfloat16(f[j] - __bfloat162float(h));
    }
    reinterpret_cast<uint2*>(g_ahi)[idx] = hi.u;
    reinterpret_cast<uint2*>(g_alo)[idx] = lo.u;
}

__global__ __launch_bounds__(256) void weff_kernel(
    const float* __restrict__ coef, const float* __restrict__ w)
{
    int idx = blockIdx.x * 256 + threadIdx.x;          // over O*I
    const float4* c4 = reinterpret_cast<const float4*>(coef + (size_t)idx * PDIM);
    float4 a = c4[0];
    float4 b = c4[1];
    float s = (((a.x + a.y) + (a.z + a.w)) + ((b.x + b.y) + (b.z + b.w))) * w[idx];
    __nv_bfloat16 h = __float2bfloat16(s);
    g_bhi[idx] = h;
    g_blo[idx] = __float2bfloat16(s - __bfloat162float(h));
}

// ============================ GEMM ============================
// Block 128x128x32, 256 threads (8 warps), warp tile 32x64.
#define BM 128
#define BN 128
#define BK 32
#define KITERS 96          // 3*1024/32

// smem: padded rows, BK+8 bf16 per row -> 80B stride (conflict-free ldmatrix)
#define ROWB 40            // bf16 per smem row
__device__ __forceinline__ uint32_t smem_u32(const void* p) {
    uint32_t a;
    asm("{ .reg .u64 t; cvta.to.shared.u64 t, %1; cvt.u32.u64 %0, t; }" : "=r"(a) : "l"(p));
    return a;
}

__device__ __forceinline__ void cp16(uint32_t dst, const void* src) {
    asm volatile("cp.async.cg.shared.global [%0], [%1], 16;" :: "r"(dst), "l"(src));
}
__device__ __forceinline__ void cp_commit() {
    asm volatile("cp.async.commit_group;");
}
template <int N>
__device__ __forceinline__ void cp_wait() {
    asm volatile("cp.async.wait_group %0;" :: "n"(N));
}

__device__ __forceinline__ void ldmx4(uint32_t* r, uint32_t addr) {
    asm volatile("ldmatrix.sync.aligned.m8n8.x4.shared.b16 {%0,%1,%2,%3}, [%4];"
                 : "=r"(r[0]), "=r"(r[1]), "=r"(r[2]), "=r"(r[3]) : "r"(addr));
}

__device__ __forceinline__ void hmma(float* c, const uint32_t* a, const uint32_t* b) {
    asm volatile(
        "mma.sync.aligned.m16n8k16.row.col.f32.bf16.bf16.f32 "
        "{%0,%1,%2,%3}, {%4,%5,%6,%7}, {%8,%9}, {%0,%1,%2,%3};"
        : "+f"(c[0]), "+f"(c[1]), "+f"(c[2]), "+f"(c[3])
        : "r"(a[0]), "r"(a[1]), "r"(a[2]), "r"(a[3]), "r"(b[0]), "r"(b[1]));
}

__global__ __launch_bounds__(256, 1) void gemm_hmma(float* __restrict__ C)
{
    __shared__ __align__(16) __nv_bfloat16 As[2][BM * ROWB];
    __shared__ __align__(16) __nv_bfloat16 Bs[2][BN * ROWB];

    const int tid = threadIdx.x;
    const int wid = tid >> 5;
    const int lid = tid & 31;
    const int warp_m = (wid & 3) * 32;     // 4 warps along M
    const int warp_n = (wid >> 2) * 64;    // 2 warps along N

    const int bm = blockIdx.y * BM;
    const int bn = blockIdx.x * BN;

    // cp.async mapping: tile = 128 rows x 64B = 512 16B-chunks.
    // 256 threads -> 2 chunks per tile per thread (rows ld_row, ld_row+64).
    const int ld_row = tid >> 2;           // 0..63
    const int ld_seg = (tid & 3) * 8;      // bf16 offset within row: 0,8,16,24

    const uint32_t asm_base[2] = {smem_u32(As[0]), smem_u32(As[1])};
    const uint32_t bsm_base[2] = {smem_u32(Bs[0]), smem_u32(Bs[1])};

    float acc[2][8][4];
#pragma unroll
    for (int i = 0; i < 2; i++)
#pragma unroll
        for (int j = 0; j < 8; j++)
#pragma unroll
            for (int q = 0; q < 4; q++) acc[i][j][q] = 0.f;

    // ldmatrix per-lane addresses
    // A: lanes 0-15 -> rows 0-15 (k 0-7), lanes 16-31 -> rows 0-15 (k 8-15)
    const int a_lrow = warp_m + (lid & 15);
    const int a_lcol = (lid >> 4) * 16;    // bytes
    // B: m0=n0-7/k0-7, m1=n0-7/k8-15, m2=n8-15/k0-7, m3=n8-15/k8-15
    const int b_lrow = warp_n + ((lid >> 4) << 3) + (lid & 7);
    const int b_lcol = ((lid >> 3) & 1) * 16;   // bytes

    auto issue_tile = [&](int kt, int buf) {
        const int seg = kt >> 5;                      // 0,1,2
        const int ko  = (kt & 31) * BK;
        const __nv_bfloat16* Ap = (seg == 1) ? g_alo : g_ahi;
        const __nv_bfloat16* Bp = (seg == 2) ? g_blo : g_bhi;
#pragma unroll
        for (int q = 0; q < 2; q++) {
            const int row = ld_row + q * 64;
            cp16(asm_base[buf] + (row * ROWB + ld_seg) * 2,
                 &Ap[(size_t)(bm + row) * IN + ko + ld_seg]);
            cp16(bsm_base[buf] + (row * ROWB + ld_seg) * 2,
                 &Bp[(size_t)(bn + row) * IN + ko + ld_seg]);
        }
        cp_commit();
    };

    issue_tile(0, 0);

    for (int kt = 0; kt < KITERS; kt++) {
        const int buf = kt & 1;
        if (kt + 1 < KITERS) {
            issue_tile(kt + 1, buf ^ 1);
            cp_wait<1>();
        } else {
            cp_wait<0>();
        }
        __syncthreads();

        const uint32_t a_base = asm_base[buf];
        const uint32_t b_base = bsm_base[buf];

#pragma unroll
        for (int h = 0; h < 2; h++) {                 // k16 halves of BK=32
            uint32_t afrag[2][4];
#pragma unroll
            for (int mt = 0; mt < 2; mt++)
                ldmx4(afrag[mt],
                      a_base + ((a_lrow + mt * 16) * ROWB) * 2 + h * 32 + a_lcol);

            uint32_t bfrag[4][4];
#pragma unroll
            for (int nt2 = 0; nt2 < 4; nt2++)
                ldmx4(bfrag[nt2],
                      b_base + ((b_lrow + nt2 * 16) * ROWB) * 2 + h * 32 + b_lcol);

#pragma unroll
            for (int mt = 0; mt < 2; mt++)
#pragma unroll
                for (int nt2 = 0; nt2 < 4; nt2++) {
                    hmma(acc[mt][nt2 * 2 + 0], afrag[mt], &bfrag[nt2][0]);
                    hmma(acc[mt][nt2 * 2 + 1], afrag[mt], &bfrag[nt2][2]);
                }
        }
        __syncthreads();
    }

    // epilogue: c fragment -> C
#pragma unroll
    for (int mt = 0; mt < 2; mt++) {
        const int row0 = bm + warp_m + mt * 16 + (lid >> 2);
#pragma unroll
        for (int nt = 0; nt < 8; nt++) {
            const int col = bn + warp_n + nt * 8 + 2 * (lid & 3);
            float2 v0 = {acc[mt][nt][0], acc[mt][nt][1]};
            float2 v1 = {acc[mt][nt][2], acc[mt][nt][3]};
            *reinterpret_cast<float2*>(&C[(size_t)row0 * OUT + col]) = v0;
            *reinterpret_cast<float2*>(&C[(size_t)(row0 + 8) * OUT + col]) = v1;
        }
    }
}

// ============================ launch ============================
extern "C" void kernel_launch(void* const* d_in, const int* in_sizes, int n_in,
                              void* d_out, int out_size)
{
    const float* x    = (const float*)d_in[0];   // [8192,1024]
    const float* coef = (const float*)d_in[1];   // [1024,1024,8]
    const float* w    = (const float*)d_in[2];   // [1024,1024]
    float* out        = (float*)d_out;           // [8192,1024]
    (void)in_sizes; (void)n_in; (void)out_size;

    xsplit_kernel<<<(BATCH * IN / 4) / 256, 256>>>(x);
    weff_kernel<<<(OUT * IN) / 256, 256>>>(coef, w);

    dim3 grid(OUT / BN, BATCH / BM);   // (8, 64)
    gemm_hmma<<<grid, 256>>>(out);
}

// round 5
// speedup vs baseline: 2.4696x; 1.6579x over previous
#include <cuda_runtime.h>
#include <cuda_bf16.h>
#include <cstdint>

// out[b,o] = x @ w_eff^T,  w_eff[o,i] = (sum_p coef[o,i,p]) * weights[o,i]
// bf16 hi/lo 3-GEMM split on HMMA (mma.sync m16n8k16), folded K=3072 loop:
//   k in [0,1024):    A_hi * B_hi
//   k in [1024,2048): A_lo * B_hi
//   k in [2048,3072): A_hi * B_lo

#define BATCH 8192
#define IN    1024
#define OUT   1024
#define PDIM  8

__device__ __nv_bfloat16 g_ahi[BATCH * IN];
__device__ __nv_bfloat16 g_alo[BATCH * IN];
__device__ __nv_bfloat16 g_bhi[OUT * IN];   // [O,I] row-major == B^T [N,K]
__device__ __nv_bfloat16 g_blo[OUT * IN];

// ============================ prep kernels ============================
__global__ __launch_bounds__(256) void xsplit_kernel(const float* __restrict__ x) {
    int idx = blockIdx.x * 256 + threadIdx.x;          // over BATCH*IN/4
    float4 v = reinterpret_cast<const float4*>(x)[idx];
    union { __nv_bfloat16 h[4]; uint2 u; } hi, lo;
    float f[4] = {v.x, v.y, v.z, v.w};
#pragma unroll
    for (int j = 0; j < 4; j++) {
        __nv_bfloat16 h = __float2bfloat16(f[j]);
        hi.h[j] = h;
        lo.h[j] = __float2bfloat16(f[j] - __bfloat162float(h));
    }
    reinterpret_cast<uint2*>(g_ahi)[idx] = hi.u;
    reinterpret_cast<uint2*>(g_alo)[idx] = lo.u;
}

__global__ __launch_bounds__(256) void weff_kernel(
    const float* __restrict__ coef, const float* __restrict__ w)
{
    int idx = blockIdx.x * 256 + threadIdx.x;          // over O*I
    const float4* c4 = reinterpret_cast<const float4*>(coef + (size_t)idx * PDIM);
    float4 a = c4[0];
    float4 b = c4[1];
    float s = (((a.x + a.y) + (a.z + a.w)) + ((b.x + b.y) + (b.z + b.w))) * w[idx];
    __nv_bfloat16 h = __float2bfloat16(s);
    g_bhi[idx] = h;
    g_blo[idx] = __float2bfloat16(s - __bfloat162float(h));
}

// ============================ GEMM ============================
// Block 256x128x32, 256 threads (8 warps, 4x2), warp tile 64x64.
// 3-stage cp.async pipeline, 1 syncthreads per k-iter.
#define BM 256
#define BN 128
#define BK 32
#define KITERS 96          // 3*1024/32
#define STAGES 3

#define ROWB 40            // bf16 per smem row (80B stride, conflict-free)
#define A_STG (BM * ROWB)  // bf16 elems per A stage
#define B_STG (BN * ROWB)
#define STG   (A_STG + B_STG)
#define SMEM_BYTES (STAGES * STG * 2)

__device__ __forceinline__ uint32_t smem_u32(const void* p) {
    uint32_t a;
    asm("{ .reg .u64 t; cvta.to.shared.u64 t, %1; cvt.u32.u64 %0, t; }" : "=r"(a) : "l"(p));
    return a;
}
__device__ __forceinline__ void cp16(uint32_t dst, const void* src) {
    asm volatile("cp.async.cg.shared.global [%0], [%1], 16;" :: "r"(dst), "l"(src));
}
__device__ __forceinline__ void cp_commit() {
    asm volatile("cp.async.commit_group;");
}
template <int N>
__device__ __forceinline__ void cp_wait() {
    asm volatile("cp.async.wait_group %0;" :: "n"(N));
}
__device__ __forceinline__ void ldmx4(uint32_t* r, uint32_t addr) {
    asm volatile("ldmatrix.sync.aligned.m8n8.x4.shared.b16 {%0,%1,%2,%3}, [%4];"
                 : "=r"(r[0]), "=r"(r[1]), "=r"(r[2]), "=r"(r[3]) : "r"(addr));
}
__device__ __forceinline__ void hmma(float* c, const uint32_t* a, const uint32_t* b) {
    asm volatile(
        "mma.sync.aligned.m16n8k16.row.col.f32.bf16.bf16.f32 "
        "{%0,%1,%2,%3}, {%4,%5,%6,%7}, {%8,%9}, {%0,%1,%2,%3};"
        : "+f"(c[0]), "+f"(c[1]), "+f"(c[2]), "+f"(c[3])
        : "r"(a[0]), "r"(a[1]), "r"(a[2]), "r"(a[3]), "r"(b[0]), "r"(b[1]));
}

__global__ __launch_bounds__(256, 1) void gemm_hmma(float* __restrict__ C)
{
    extern __shared__ __nv_bfloat16 smem[];

    const int tid = threadIdx.x;
    const int wid = tid >> 5;
    const int lid = tid & 31;
    const int warp_m = (wid & 3) * 64;     // 4 warps along M
    const int warp_n = (wid >> 2) * 64;    // 2 warps along N

    const int bm = blockIdx.y * BM;
    const int bn = blockIdx.x * BN;

    // cp.async mapping: A stage = 256 rows x 64B = 1024 chunks (4/thread),
    //                   B stage = 128 rows x 64B = 512 chunks (2/thread)
    const int ld_row = tid >> 2;           // 0..63
    const int ld_seg = (tid & 3) * 8;      // bf16 offset in row: 0,8,16,24

    uint32_t stg_base[STAGES];
#pragma unroll
    for (int s = 0; s < STAGES; s++) stg_base[s] = smem_u32(smem + s * STG);

    float acc[4][8][4];
#pragma unroll
    for (int i = 0; i < 4; i++)
#pragma unroll
        for (int j = 0; j < 8; j++)
#pragma unroll
            for (int q = 0; q < 4; q++) acc[i][j][q] = 0.f;

    // ldmatrix lane addressing (byte offsets within tile)
    const int a_lrow = warp_m + (lid & 15);
    const int a_lcol = (lid >> 4) * 16;
    const int b_lrow = warp_n + ((lid >> 4) << 3) + (lid & 7);
    const int b_lcol = ((lid >> 3) & 1) * 16;

    auto issue_tile = [&](int kt, int stage) {
        const int seg = kt >> 5;                      // 0,1,2
        const int ko  = (kt & 31) * BK;
        const __nv_bfloat16* Ap = (seg == 1) ? g_alo : g_ahi;
        const __nv_bfloat16* Bp = (seg == 2) ? g_blo : g_bhi;
        const uint32_t ab = stg_base[stage];
        const uint32_t bb = ab + A_STG * 2;
#pragma unroll
        for (int q = 0; q < 4; q++) {
            const int row = ld_row + q * 64;
            cp16(ab + (row * ROWB + ld_seg) * 2,
                 &Ap[(size_t)(bm + row) * IN + ko + ld_seg]);
        }
#pragma unroll
        for (int q = 0; q < 2; q++) {
            const int row = ld_row + q * 64;
            cp16(bb + (row * ROWB + ld_seg) * 2,
                 &Bp[(size_t)(bn + row) * IN + ko + ld_seg]);
        }
        cp_commit();
    };

    issue_tile(0, 0);
    issue_tile(1, 1);

    for (int kt = 0; kt < KITERS; kt++) {
        const int stage = kt % STAGES;
        cp_wait<1>();          // tile kt complete (kt+1 may be in flight)
        __syncthreads();

        const uint32_t a_base = stg_base[stage];
        const uint32_t b_base = a_base + A_STG * 2;

#pragma unroll
        for (int h = 0; h < 2; h++) {                 // two k16 halves of BK=32
            uint32_t afrag[4][4];
#pragma unroll
            for (int mt = 0; mt < 4; mt++)
                ldmx4(afrag[mt],
                      a_base + ((a_lrow + mt * 16) * ROWB) * 2 + h * 32 + a_lcol);

            uint32_t bfrag[4][4];
#pragma unroll
            for (int nt2 = 0; nt2 < 4; nt2++)
                ldmx4(bfrag[nt2],
                      b_base + ((b_lrow + nt2 * 16) * ROWB) * 2 + h * 32 + b_lcol);

#pragma unroll
            for (int mt = 0; mt < 4; mt++)
#pragma unroll
                for (int nt2 = 0; nt2 < 4; nt2++) {
                    hmma(acc[mt][nt2 * 2 + 0], afrag[mt], &bfrag[nt2][0]);
                    hmma(acc[mt][nt2 * 2 + 1], afrag[mt], &bfrag[nt2][2]);
                }
        }

        // issue tile kt+2 into the stage tile kt-1 occupied (safe: consumed,
        // and everyone passed this iteration's barrier). Wraparound keeps the
        // cp.async group count uniform so cp_wait<1> above is always correct.
        issue_tile((kt + 2) % KITERS, (kt + 2) % STAGES);
    }

    // epilogue
#pragma unroll
    for (int mt = 0; mt < 4; mt++) {
        const int row0 = bm + warp_m + mt * 16 + (lid >> 2);
#pragma unroll
        for (int nt = 0; nt < 8; nt++) {
            const int col = bn + warp_n + nt * 8 + 2 * (lid & 3);
            float2 v0 = {acc[mt][nt][0], acc[mt][nt][1]};
            float2 v1 = {acc[mt][nt][2], acc[mt][nt][3]};
            *reinterpret_cast<float2*>(&C[(size_t)row0 * OUT + col]) = v0;
            *reinterpret_cast<float2*>(&C[(size_t)(row0 + 8) * OUT + col]) = v1;
        }
    }
}

// ============================ launch ============================
extern "C" void kernel_launch(void* const* d_in, const int* in_sizes, int n_in,
                              void* d_out, int out_size)
{
    const float* x    = (const float*)d_in[0];   // [8192,1024]
    const float* coef = (const float*)d_in[1];   // [1024,1024,8]
    const float* w    = (const float*)d_in[2];   // [1024,1024]
    float* out        = (float*)d_out;           // [8192,1024]
    (void)in_sizes; (void)n_in; (void)out_size;

    static int attr_set = 0;
    if (!attr_set) {
        cudaFuncSetAttribute(gemm_hmma,
                             cudaFuncAttributeMaxDynamicSharedMemorySize, SMEM_BYTES);
        attr_set = 1;
    }

    xsplit_kernel<<<(BATCH * IN / 4) / 256, 256>>>(x);
    weff_kernel<<<(OUT * IN) / 256, 256>>>(coef, w);

    dim3 grid(OUT / BN, BATCH / BM);   // (8, 32) = 256 CTAs
    gemm_hmma<<<grid, 256, SMEM_BYTES>>>(out);
}

// round 6
// speedup vs baseline: 3.1922x; 1.2926x over previous
#include <cuda_runtime.h>
#include <cuda_fp16.h>
#include <cstdint>

// out[b,o] = x @ w_eff^T,  w_eff[o,i] = (sum_p coef[o,i,p]) * weights[o,i]
// fp16 hi/lo 2-GEMM split on HMMA (mma.sync m16n8k16 f16):
//   C = A_hi*B_hi + A_lo*B_hi      (A_hi*B_lo term dropped: ~1.5e-4 rel)
// folded into one K=2048 loop.

#define BATCH 8192
#define IN    1024
#define OUT   1024
#define PDIM  8

__device__ __half g_ahi[BATCH * IN];
__device__ __half g_alo[BATCH * IN];
__device__ __half g_bhi[OUT * IN];   // [O,I] row-major == B^T [N,K]

// ============================ prep kernels ============================
__global__ __launch_bounds__(256) void xsplit_kernel(const float* __restrict__ x) {
    int idx = blockIdx.x * 256 + threadIdx.x;          // over BATCH*IN/4
    float4 v = reinterpret_cast<const float4*>(x)[idx];
    union { __half h[4]; uint2 u; } hi, lo;
    float f[4] = {v.x, v.y, v.z, v.w};
#pragma unroll
    for (int j = 0; j < 4; j++) {
        __half h = __float2half_rn(f[j]);
        hi.h[j] = h;
        lo.h[j] = __float2half_rn(f[j] - __half2float(h));  // exact residual, fp16-rounded
    }
    reinterpret_cast<uint2*>(g_ahi)[idx] = hi.u;
    reinterpret_cast<uint2*>(g_alo)[idx] = lo.u;
}

__global__ __launch_bounds__(256) void weff_kernel(
    const float* __restrict__ coef, const float* __restrict__ w)
{
    int idx = blockIdx.x * 256 + threadIdx.x;          // over O*I
    const float4* c4 = reinterpret_cast<const float4*>(coef + (size_t)idx * PDIM);
    float4 a = c4[0];
    float4 b = c4[1];
    float s = (((a.x + a.y) + (a.z + a.w)) + ((b.x + b.y) + (b.z + b.w))) * w[idx];
    g_bhi[idx] = __float2half_rn(s);
}

// ============================ GEMM ============================
// Block 256x128x32, 256 threads (8 warps, 4x2), warp tile 64x64.
// 4-stage cp.async pipeline (issue-ahead 3), 1 syncthreads per k-iter.
#define BM 256
#define BN 128
#define BK 32
#define KITERS 64          // 2*1024/32
#define STAGES 4

#define ROWB 40            // halfs per smem row (80B stride, conflict-free)
#define A_STG (BM * ROWB)
#define B_STG (BN * ROWB)
#define STG   (A_STG + B_STG)
#define SMEM_BYTES (STAGES * STG * 2)   // 122880

__device__ __forceinline__ uint32_t smem_u32(const void* p) {
    uint32_t a;
    asm("{ .reg .u64 t; cvta.to.shared.u64 t, %1; cvt.u32.u64 %0, t; }" : "=r"(a) : "l"(p));
    return a;
}
__device__ __forceinline__ void cp16(uint32_t dst, const void* src) {
    asm volatile("cp.async.cg.shared.global [%0], [%1], 16;" :: "r"(dst), "l"(src));
}
__device__ __forceinline__ void cp_commit() {
    asm volatile("cp.async.commit_group;");
}
template <int N>
__device__ __forceinline__ void cp_wait() {
    asm volatile("cp.async.wait_group %0;" :: "n"(N));
}
__device__ __forceinline__ void ldmx4(uint32_t* r, uint32_t addr) {
    asm volatile("ldmatrix.sync.aligned.m8n8.x4.shared.b16 {%0,%1,%2,%3}, [%4];"
                 : "=r"(r[0]), "=r"(r[1]), "=r"(r[2]), "=r"(r[3]) : "r"(addr));
}
__device__ __forceinline__ void hmma(float* c, const uint32_t* a, const uint32_t* b) {
    asm volatile(
        "mma.sync.aligned.m16n8k16.row.col.f32.f16.f16.f32 "
        "{%0,%1,%2,%3}, {%4,%5,%6,%7}, {%8,%9}, {%0,%1,%2,%3};"
        : "+f"(c[0]), "+f"(c[1]), "+f"(c[2]), "+f"(c[3])
        : "r"(a[0]), "r"(a[1]), "r"(a[2]), "r"(a[3]), "r"(b[0]), "r"(b[1]));
}

__global__ __launch_bounds__(256, 1) void gemm_hmma(float* __restrict__ C)
{
    extern __shared__ __half smem[];

    const int tid = threadIdx.x;
    const int wid = tid >> 5;
    const int lid = tid & 31;
    const int warp_m = (wid & 3) * 64;     // 4 warps along M
    const int warp_n = (wid >> 2) * 64;    // 2 warps along N

    const int bm = blockIdx.y * BM;
    const int bn = blockIdx.x * BN;

    // cp.async mapping: A stage = 256 rows x 64B (4 chunks/thread),
    //                   B stage = 128 rows x 64B (2 chunks/thread)
    const int ld_row = tid >> 2;           // 0..63
    const int ld_seg = (tid & 3) * 8;      // half offset in row: 0,8,16,24

    uint32_t stg_base[STAGES];
#pragma unroll
    for (int s = 0; s < STAGES; s++) stg_base[s] = smem_u32(smem + s * STG);

    float acc[4][8][4];
#pragma unroll
    for (int i = 0; i < 4; i++)
#pragma unroll
        for (int j = 0; j < 8; j++)
#pragma unroll
            for (int q = 0; q < 4; q++) acc[i][j][q] = 0.f;

    // ldmatrix lane addressing (byte offsets within tile)
    const int a_lrow = warp_m + (lid & 15);
    const int a_lcol = (lid >> 4) * 16;
    const int b_lrow = warp_n + ((lid >> 4) << 3) + (lid & 7);
    const int b_lcol = ((lid >> 3) & 1) * 16;

    auto issue_tile = [&](int kt, int stage) {
        const int seg = kt >> 5;                      // 0: A_hi, 1: A_lo
        const int ko  = (kt & 31) * BK;
        const __half* Ap = seg ? g_alo : g_ahi;
        const uint32_t ab = stg_base[stage];
        const uint32_t bb = ab + A_STG * 2;
#pragma unroll
        for (int q = 0; q < 4; q++) {
            const int row = ld_row + q * 64;
            cp16(ab + (row * ROWB + ld_seg) * 2,
                 &Ap[(size_t)(bm + row) * IN + ko + ld_seg]);
        }
#pragma unroll
        for (int q = 0; q < 2; q++) {
            const int row = ld_row + q * 64;
            cp16(bb + (row * ROWB + ld_seg) * 2,
                 &g_bhi[(size_t)(bn + row) * IN + ko + ld_seg]);
        }
        cp_commit();
    };

    issue_tile(0, 0);
    issue_tile(1, 1);
    issue_tile(2, 2);

    for (int kt = 0; kt < KITERS; kt++) {
        const int stage = kt % STAGES;
        cp_wait<2>();          // tile kt complete (kt+1, kt+2 may be in flight)
        __syncthreads();

        const uint32_t a_base = stg_base[stage];
        const uint32_t b_base = a_base + A_STG * 2;

#pragma unroll
        for (int h = 0; h < 2; h++) {                 // two k16 halves of BK=32
            uint32_t afrag[4][4];
#pragma unroll
            for (int mt = 0; mt < 4; mt++)
                ldmx4(afrag[mt],
                      a_base + ((a_lrow + mt * 16) * ROWB) * 2 + h * 32 + a_lcol);

            uint32_t bfrag[4][4];
#pragma unroll
            for (int nt2 = 0; nt2 < 4; nt2++)
                ldmx4(bfrag[nt2],
                      b_base + ((b_lrow + nt2 * 16) * ROWB) * 2 + h * 32 + b_lcol);

#pragma unroll
            for (int mt = 0; mt < 4; mt++)
#pragma unroll
                for (int nt2 = 0; nt2 < 4; nt2++) {
                    hmma(acc[mt][nt2 * 2 + 0], afrag[mt], &bfrag[nt2][0]);
                    hmma(acc[mt][nt2 * 2 + 1], afrag[mt], &bfrag[nt2][2]);
                }
        }

        // issue tile kt+3 into the stage consumed at iter kt-1 (safe: all
        // warps passed this iteration's barrier after finishing its reads).
        // Wraparound keeps group counts uniform so cp_wait<2> stays aligned.
        issue_tile((kt + 3) % KITERS, (kt + 3) % STAGES);
    }

    // epilogue
#pragma unroll
    for (int mt = 0; mt < 4; mt++) {
        const int row0 = bm + warp_m + mt * 16 + (lid >> 2);
#pragma unroll
        for (int nt = 0; nt < 8; nt++) {
            const int col = bn + warp_n + nt * 8 + 2 * (lid & 3);
            float2 v0 = {acc[mt][nt][0], acc[mt][nt][1]};
            float2 v1 = {acc[mt][nt][2], acc[mt][nt][3]};
            *reinterpret_cast<float2*>(&C[(size_t)row0 * OUT + col]) = v0;
            *reinterpret_cast<float2*>(&C[(size_t)(row0 + 8) * OUT + col]) = v1;
        }
    }
}

// ============================ launch ============================
extern "C" void kernel_launch(void* const* d_in, const int* in_sizes, int n_in,
                              void* d_out, int out_size)
{
    const float* x    = (const float*)d_in[0];   // [8192,1024]
    const float* coef = (const float*)d_in[1];   // [1024,1024,8]
    const float* w    = (const float*)d_in[2];   // [1024,1024]
    float* out        = (float*)d_out;           // [8192,1024]
    (void)in_sizes; (void)n_in; (void)out_size;

    static int attr_set = 0;
    if (!attr_set) {
        cudaFuncSetAttribute(gemm_hmma,
                             cudaFuncAttributeMaxDynamicSharedMemorySize, SMEM_BYTES);
        attr_set = 1;
    }

    xsplit_kernel<<<(BATCH * IN / 4) / 256, 256>>>(x);
    weff_kernel<<<(OUT * IN) / 256, 256>>>(coef, w);

    dim3 grid(OUT / BN, BATCH / BM);   // (8, 32) = 256 CTAs
    gemm_hmma<<<grid, 256, SMEM_BYTES>>>(out);
}

// round 7
// speedup vs baseline: 5.4711x; 1.7139x over previous
#include <cuda_runtime.h>
#include <cuda_fp16.h>
#include <cstdint>

// out[b,o] = x @ w_eff^T,  w_eff[o,i] = (sum_p coef[o,i,p]) * weights[o,i]
// Single fp16 GEMM on HMMA (mma.sync m16n8k16 f16, fp32 accum):
//   C = fp16(x) @ fp16(w_eff)^T
// Error model (calibrated R6): dropped A/B residual terms each ~2.07e-4,
// independent -> ~2.9e-4 total, threshold 1e-3.

#define BATCH 8192
#define IN    1024
#define OUT   1024
#define PDIM  8

__device__ __half g_ahi[BATCH * IN];
__device__ __half g_bhi[OUT * IN];   // [O,I] row-major == B^T [N,K]

// ============================ fused prep kernel ============================
// blocks [0, XBLKS): convert x -> fp16          (8192*1024/4 items /256)
// blocks [XBLKS, XBLKS+WBLKS): build w_eff fp16 (1024*1024 items /256)
#define XBLKS ((BATCH * IN / 4) / 256)
#define WBLKS ((OUT * IN) / 256)

__global__ __launch_bounds__(256) void prep_kernel(
    const float* __restrict__ x,
    const float* __restrict__ coef,
    const float* __restrict__ w)
{
    if (blockIdx.x < XBLKS) {
        int idx = blockIdx.x * 256 + threadIdx.x;      // over BATCH*IN/4
        float4 v = reinterpret_cast<const float4*>(x)[idx];
        union { __half h[4]; uint2 u; } hi;
        hi.h[0] = __float2half_rn(v.x);
        hi.h[1] = __float2half_rn(v.y);
        hi.h[2] = __float2half_rn(v.z);
        hi.h[3] = __float2half_rn(v.w);
        reinterpret_cast<uint2*>(g_ahi)[idx] = hi.u;
    } else {
        int idx = (blockIdx.x - XBLKS) * 256 + threadIdx.x;   // over O*I
        const float4* c4 = reinterpret_cast<const float4*>(coef + (size_t)idx * PDIM);
        float4 a = c4[0];
        float4 b = c4[1];
        float s = (((a.x + a.y) + (a.z + a.w)) + ((b.x + b.y) + (b.z + b.w))) * w[idx];
        g_bhi[idx] = __float2half_rn(s);
    }
}

// ============================ GEMM ============================
// Block 256x128x32, 256 threads (8 warps, 4x2), warp tile 64x64.
// 4-stage cp.async pipeline (issue-ahead 3), 1 syncthreads per k-iter.
#define BM 256
#define BN 128
#define BK 32
#define KITERS 32          // 1024/32
#define STAGES 4

#define ROWB 40            // halfs per smem row (80B stride, conflict-free)
#define A_STG (BM * ROWB)
#define B_STG (BN * ROWB)
#define STG   (A_STG + B_STG)
#define SMEM_BYTES (STAGES * STG * 2)   // 122880

__device__ __forceinline__ uint32_t smem_u32(const void* p) {
    uint32_t a;
    asm("{ .reg .u64 t; cvta.to.shared.u64 t, %1; cvt.u32.u64 %0, t; }" : "=r"(a) : "l"(p));
    return a;
}
__device__ __forceinline__ void cp16(uint32_t dst, const void* src) {
    asm volatile("cp.async.cg.shared.global [%0], [%1], 16;" :: "r"(dst), "l"(src));
}
__device__ __forceinline__ void cp_commit() {
    asm volatile("cp.async.commit_group;");
}
template <int N>
__device__ __forceinline__ void cp_wait() {
    asm volatile("cp.async.wait_group %0;" :: "n"(N));
}
__device__ __forceinline__ void ldmx4(uint32_t* r, uint32_t addr) {
    asm volatile("ldmatrix.sync.aligned.m8n8.x4.shared.b16 {%0,%1,%2,%3}, [%4];"
                 : "=r"(r[0]), "=r"(r[1]), "=r"(r[2]), "=r"(r[3]) : "r"(addr));
}
__device__ __forceinline__ void hmma(float* c, const uint32_t* a, const uint32_t* b) {
    asm volatile(
        "mma.sync.aligned.m16n8k16.row.col.f32.f16.f16.f32 "
        "{%0,%1,%2,%3}, {%4,%5,%6,%7}, {%8,%9}, {%0,%1,%2,%3};"
        : "+f"(c[0]), "+f"(c[1]), "+f"(c[2]), "+f"(c[3])
        : "r"(a[0]), "r"(a[1]), "r"(a[2]), "r"(a[3]), "r"(b[0]), "r"(b[1]));
}

__global__ __launch_bounds__(256, 1) void gemm_hmma(float* __restrict__ C)
{
    extern __shared__ __half smem[];

    const int tid = threadIdx.x;
    const int wid = tid >> 5;
    const int lid = tid & 31;
    const int warp_m = (wid & 3) * 64;     // 4 warps along M
    const int warp_n = (wid >> 2) * 64;    // 2 warps along N

    const int bm = blockIdx.y * BM;
    const int bn = blockIdx.x * BN;

    // cp.async mapping: A stage = 256 rows x 64B (4 chunks/thread),
    //                   B stage = 128 rows x 64B (2 chunks/thread)
    const int ld_row = tid >> 2;           // 0..63
    const int ld_seg = (tid & 3) * 8;      // half offset in row: 0,8,16,24

    uint32_t stg_base[STAGES];
#pragma unroll
    for (int s = 0; s < STAGES; s++) stg_base[s] = smem_u32(smem + s * STG);

    float acc[4][8][4];
#pragma unroll
    for (int i = 0; i < 4; i++)
#pragma unroll
        for (int j = 0; j < 8; j++)
#pragma unroll
            for (int q = 0; q < 4; q++) acc[i][j][q] = 0.f;

    // ldmatrix lane addressing (byte offsets within tile)
    const int a_lrow = warp_m + (lid & 15);
    const int a_lcol = (lid >> 4) * 16;
    const int b_lrow = warp_n + ((lid >> 4) << 3) + (lid & 7);
    const int b_lcol = ((lid >> 3) & 1) * 16;

    auto issue_tile = [&](int kt, int stage) {
        const int ko = kt * BK;
        const uint32_t ab = stg_base[stage];
        const uint32_t bb = ab + A_STG * 2;
#pragma unroll
        for (int q = 0; q < 4; q++) {
            const int row = ld_row + q * 64;
            cp16(ab + (row * ROWB + ld_seg) * 2,
                 &g_ahi[(size_t)(bm + row) * IN + ko + ld_seg]);
        }
#pragma unroll
        for (int q = 0; q < 2; q++) {
            const int row = ld_row + q * 64;
            cp16(bb + (row * ROWB + ld_seg) * 2,
                 &g_bhi[(size_t)(bn + row) * IN + ko + ld_seg]);
        }
        cp_commit();
    };

    issue_tile(0, 0);
    issue_tile(1, 1);
    issue_tile(2, 2);

    for (int kt = 0; kt < KITERS; kt++) {
        const int stage = kt % STAGES;
        cp_wait<2>();          // tile kt complete (kt+1, kt+2 may be in flight)
        __syncthreads();

        const uint32_t a_base = stg_base[stage];
        const uint32_t b_base = a_base + A_STG * 2;

#pragma unroll
        for (int h = 0; h < 2; h++) {                 // two k16 halves of BK=32
            uint32_t afrag[4][4];
#pragma unroll
            for (int mt = 0; mt < 4; mt++)
                ldmx4(afrag[mt],
                      a_base + ((a_lrow + mt * 16) * ROWB) * 2 + h * 32 + a_lcol);

            uint32_t bfrag[4][4];
#pragma unroll
            for (int nt2 = 0; nt2 < 4; nt2++)
                ldmx4(bfrag[nt2],
                      b_base + ((b_lrow + nt2 * 16) * ROWB) * 2 + h * 32 + b_lcol);

#pragma unroll
            for (int mt = 0; mt < 4; mt++)
#pragma unroll
                for (int nt2 = 0; nt2 < 4; nt2++) {
                    hmma(acc[mt][nt2 * 2 + 0], afrag[mt], &bfrag[nt2][0]);
                    hmma(acc[mt][nt2 * 2 + 1], afrag[mt], &bfrag[nt2][2]);
                }
        }

        // issue tile kt+3 into the stage consumed at iter kt-1 (safe: all
        // warps passed this iteration's barrier after finishing its reads).
        // Wraparound keeps group counts uniform so cp_wait<2> stays aligned.
        issue_tile((kt + 3) % KITERS, (kt + 3) % STAGES);
    }

    // epilogue
#pragma unroll
    for (int mt = 0; mt < 4; mt++) {
        const int row0 = bm + warp_m + mt * 16 + (lid >> 2);
#pragma unroll
        for (int nt = 0; nt < 8; nt++) {
            const int col = bn + warp_n + nt * 8 + 2 * (lid & 3);
            float2 v0 = {acc[mt][nt][0], acc[mt][nt][1]};
            float2 v1 = {acc[mt][nt][2], acc[mt][nt][3]};
            *reinterpret_cast<float2*>(&C[(size_t)row0 * OUT + col]) = v0;
            *reinterpret_cast<float2*>(&C[(size_t)(row0 + 8) * OUT + col]) = v1;
        }
    }
}

// ============================ launch ============================
extern "C" void kernel_launch(void* const* d_in, const int* in_sizes, int n_in,
                              void* d_out, int out_size)
{
    const float* x    = (const float*)d_in[0];   // [8192,1024]
    const float* coef = (const float*)d_in[1];   // [1024,1024,8]
    const float* w    = (const float*)d_in[2];   // [1024,1024]
    float* out        = (float*)d_out;           // [8192,1024]
    (void)in_sizes; (void)n_in; (void)out_size;

    static int attr_set = 0;
    if (!attr_set) {
        cudaFuncSetAttribute(gemm_hmma,
                             cudaFuncAttributeMaxDynamicSharedMemorySize, SMEM_BYTES);
        attr_set = 1;
    }

    prep_kernel<<<XBLKS + WBLKS, 256>>>(x, coef, w);

    dim3 grid(OUT / BN, BATCH / BM);   // (8, 32) = 256 CTAs
    gemm_hmma<<<grid, 256, SMEM_BYTES>>>(out);
}

// round 8
// speedup vs baseline: 6.1854x; 1.1305x over previous
#include <cuda_runtime.h>
#include <cuda_fp16.h>
#include <cstdint>

// out[b,o] = x @ w_eff^T,  w_eff[o,i] = (sum_p coef[o,i,p]) * weights[o,i]
// Single fp16 GEMM on HMMA (m16n8k16, fp32 accum): C = fp16(x) @ fp16(w_eff)^T
// rel_err ~2.9e-4 (calibrated R6/R7), threshold 1e-3.

#define BATCH 8192
#define IN    1024
#define OUT   1024
#define PDIM  8

__device__ __half g_ahi[BATCH * IN];
__device__ __half g_bhi[OUT * IN];   // [O,I] row-major == B^T [N,K]

// ============================ fused prep kernel ============================
#define XBLKS ((BATCH * IN / 4) / 256)
#define WBLKS ((OUT * IN) / 256)

__global__ __launch_bounds__(256) void prep_kernel(
    const float* __restrict__ x,
    const float* __restrict__ coef,
    const float* __restrict__ w)
{
    if (blockIdx.x < XBLKS) {
        int idx = blockIdx.x * 256 + threadIdx.x;      // over BATCH*IN/4
        float4 v = reinterpret_cast<const float4*>(x)[idx];
        union { __half h[4]; uint2 u; } hi;
        hi.h[0] = __float2half_rn(v.x);
        hi.h[1] = __float2half_rn(v.y);
        hi.h[2] = __float2half_rn(v.z);
        hi.h[3] = __float2half_rn(v.w);
        reinterpret_cast<uint2*>(g_ahi)[idx] = hi.u;
    } else {
        int idx = (blockIdx.x - XBLKS) * 256 + threadIdx.x;   // over O*I
        const float4* c4 = reinterpret_cast<const float4*>(coef + (size_t)idx * PDIM);
        float4 a = c4[0];
        float4 b = c4[1];
        float s = (((a.x + a.y) + (a.z + a.w)) + ((b.x + b.y) + (b.z + b.w))) * w[idx];
        g_bhi[idx] = __float2half_rn(s);
    }
}

// ============================ GEMM ============================
// Block 256x128x64, 256 threads (8 warps, 4x2), warp tile 64x64.
// 3-stage cp.async pipeline, 1 syncthreads per k-iter (16 iters).
// Fragment double-buffering: LDSM for k16-half h+1 issued before HMMAs of h.
#define BM 256
#define BN 128
#define BK 64
#define KITERS 16          // 1024/64
#define STAGES 3
#define HALVES 4           // k16 halves per BK=64

#define ROWB 72            // halfs per smem row (144B stride; 4r mod 32 banks distinct)
#define A_STG (BM * ROWB)
#define B_STG (BN * ROWB)
#define STG   (A_STG + B_STG)
#define SMEM_BYTES (STAGES * STG * 2)   // 165,888

__device__ __forceinline__ uint32_t smem_u32(const void* p) {
    uint32_t a;
    asm("{ .reg .u64 t; cvta.to.shared.u64 t, %1; cvt.u32.u64 %0, t; }" : "=r"(a) : "l"(p));
    return a;
}
__device__ __forceinline__ void cp16(uint32_t dst, const void* src) {
    asm volatile("cp.async.cg.shared.global [%0], [%1], 16;" :: "r"(dst), "l"(src));
}
__device__ __forceinline__ void cp_commit() {
    asm volatile("cp.async.commit_group;");
}
template <int N>
__device__ __forceinline__ void cp_wait() {
    asm volatile("cp.async.wait_group %0;" :: "n"(N));
}
__device__ __forceinline__ void ldmx4(uint32_t* r, uint32_t addr) {
    asm volatile("ldmatrix.sync.aligned.m8n8.x4.shared.b16 {%0,%1,%2,%3}, [%4];"
                 : "=r"(r[0]), "=r"(r[1]), "=r"(r[2]), "=r"(r[3]) : "r"(addr));
}
__device__ __forceinline__ void hmma(float* c, const uint32_t* a, const uint32_t* b) {
    asm volatile(
        "mma.sync.aligned.m16n8k16.row.col.f32.f16.f16.f32 "
        "{%0,%1,%2,%3}, {%4,%5,%6,%7}, {%8,%9}, {%0,%1,%2,%3};"
        : "+f"(c[0]), "+f"(c[1]), "+f"(c[2]), "+f"(c[3])
        : "r"(a[0]), "r"(a[1]), "r"(a[2]), "r"(a[3]), "r"(b[0]), "r"(b[1]));
}

__global__ __launch_bounds__(256, 1) void gemm_hmma(float* __restrict__ C)
{
    extern __shared__ __half smem[];

    const int tid = threadIdx.x;
    const int wid = tid >> 5;
    const int lid = tid & 31;
    const int warp_m = (wid & 3) * 64;     // 4 warps along M
    const int warp_n = (wid >> 2) * 64;    // 2 warps along N

    const int bm = blockIdx.y * BM;
    const int bn = blockIdx.x * BN;

    // cp.async mapping: rows are 128B of data; 8 x 16B chunks per row.
    // A stage = 256 rows (8 chunks/thread over 32-row groups),
    // B stage = 128 rows (4 chunks/thread).
    const int ld_row = tid >> 3;           // 0..31
    const int ld_seg = (tid & 7) * 8;      // half offset in row: 0..56

    uint32_t stg_base[STAGES];
#pragma unroll
    for (int s = 0; s < STAGES; s++) stg_base[s] = smem_u32(smem + s * STG);

    float acc[4][8][4];
#pragma unroll
    for (int i = 0; i < 4; i++)
#pragma unroll
        for (int j = 0; j < 8; j++)
#pragma unroll
            for (int q = 0; q < 4; q++) acc[i][j][q] = 0.f;

    // ldmatrix lane addressing (byte offsets within tile)
    const int a_lrow = warp_m + (lid & 15);
    const int a_lcol = (lid >> 4) * 16;
    const int b_lrow = warp_n + ((lid >> 4) << 3) + (lid & 7);
    const int b_lcol = ((lid >> 3) & 1) * 16;

    auto issue_tile = [&](int kt, int stage) {
        const int ko = kt * BK;
        const uint32_t ab = stg_base[stage];
        const uint32_t bb = ab + A_STG * 2;
#pragma unroll
        for (int q = 0; q < 8; q++) {
            const int row = ld_row + q * 32;
            cp16(ab + (row * ROWB + ld_seg) * 2,
                 &g_ahi[(size_t)(bm + row) * IN + ko + ld_seg]);
        }
#pragma unroll
        for (int q = 0; q < 4; q++) {
            const int row = ld_row + q * 32;
            cp16(bb + (row * ROWB + ld_seg) * 2,
                 &g_bhi[(size_t)(bn + row) * IN + ko + ld_seg]);
        }
        cp_commit();
    };

    issue_tile(0, 0);
    issue_tile(1, 1);

    for (int kt = 0; kt < KITERS; kt++) {
        const int stage = kt % STAGES;
        cp_wait<1>();          // tile kt complete (kt+1 may be in flight)
        __syncthreads();

        const uint32_t a_base = stg_base[stage];
        const uint32_t b_base = a_base + A_STG * 2;

        // fragment double buffers
        uint32_t afrag[2][4][4];
        uint32_t bfrag[2][4][4];

        // prefetch h=0
#pragma unroll
        for (int mt = 0; mt < 4; mt++)
            ldmx4(afrag[0][mt],
                  a_base + ((a_lrow + mt * 16) * ROWB) * 2 + a_lcol);
#pragma unroll
        for (int nt2 = 0; nt2 < 4; nt2++)
            ldmx4(bfrag[0][nt2],
                  b_base + ((b_lrow + nt2 * 16) * ROWB) * 2 + b_lcol);

#pragma unroll
        for (int h = 0; h < HALVES; h++) {
            const int cur = h & 1;
            if (h + 1 < HALVES) {
                const int nxt = cur ^ 1;
                const int off = (h + 1) * 32;
#pragma unroll
                for (int mt = 0; mt < 4; mt++)
                    ldmx4(afrag[nxt][mt],
                          a_base + ((a_lrow + mt * 16) * ROWB) * 2 + off + a_lcol);
#pragma unroll
                for (int nt2 = 0; nt2 < 4; nt2++)
                    ldmx4(bfrag[nxt][nt2],
                          b_base + ((b_lrow + nt2 * 16) * ROWB) * 2 + off + b_lcol);
            }
#pragma unroll
            for (int mt = 0; mt < 4; mt++)
#pragma unroll
                for (int nt2 = 0; nt2 < 4; nt2++) {
                    hmma(acc[mt][nt2 * 2 + 0], afrag[cur][mt], &bfrag[cur][nt2][0]);
                    hmma(acc[mt][nt2 * 2 + 1], afrag[cur][mt], &bfrag[cur][nt2][2]);
                }
        }

        // issue tile kt+2 into the stage consumed at iter kt-1 (all warps
        // passed this iteration's barrier). Wraparound keeps cp.async group
        // counts uniform so cp_wait<1> stays aligned.
        issue_tile((kt + 2) % KITERS, (kt + 2) % STAGES);
    }

    // epilogue
#pragma unroll
    for (int mt = 0; mt < 4; mt++) {
        const int row0 = bm + warp_m + mt * 16 + (lid >> 2);
#pragma unroll
        for (int nt = 0; nt < 8; nt++) {
            const int col = bn + warp_n + nt * 8 + 2 * (lid & 3);
            float2 v0 = {acc[mt][nt][0], acc[mt][nt][1]};
            float2 v1 = {acc[mt][nt][2], acc[mt][nt][3]};
            *reinterpret_cast<float2*>(&C[(size_t)row0 * OUT + col]) = v0;
            *reinterpret_cast<float2*>(&C[(size_t)(row0 + 8) * OUT + col]) = v1;
        }
    }
}

// ============================ launch ============================
extern "C" void kernel_launch(void* const* d_in, const int* in_sizes, int n_in,
                              void* d_out, int out_size)
{
    const float* x    = (const float*)d_in[0];   // [8192,1024]
    const float* coef = (const float*)d_in[1];   // [1024,1024,8]
    const float* w    = (const float*)d_in[2];   // [1024,1024]
    float* out        = (float*)d_out;           // [8192,1024]
    (void)in_sizes; (void)n_in; (void)out_size;

    static int attr_set = 0;
    if (!attr_set) {
        cudaFuncSetAttribute(gemm_hmma,
                             cudaFuncAttributeMaxDynamicSharedMemorySize, SMEM_BYTES);
        attr_set = 1;
    }

    prep_kernel<<<XBLKS + WBLKS, 256>>>(x, coef, w);

    dim3 grid(OUT / BN, BATCH / BM);   // (8, 32) = 256 CTAs
    gemm_hmma<<<grid, 256, SMEM_BYTES>>>(out);
}